// round 8
// baseline (speedup 1.0000x reference)
#include <cuda_runtime.h>

#define NQ   12
#define DIM  4096
#define NL   6
#define TPB  256

// padded smem slot to avoid bank conflicts in the stride-16 pass
#define SLOT(i) ((i) + ((i) >> 4))

__device__ __forceinline__ float2 cmul(const float2 a, const float2 b) {
    float2 r;
    r.x = fmaf(a.x, b.x, -a.y * b.y);
    r.y = fmaf(a.x, b.y,  a.y * b.x);
    return r;
}

// Real Ry butterfly on pairing bit P: [c -s; s c] applied to (re,im) independently.
template <int P>
__device__ __forceinline__ void apply_ry(float2 v[16], const float c, const float s) {
#pragma unroll
    for (int j0 = 0; j0 < 16; ++j0) {
        if (j0 & (1 << P)) continue;
        const int j1 = j0 | (1 << P);
        const float2 a = v[j0], b = v[j1];
        float2 n0, n1;
        n0.x = fmaf(c, a.x, -s * b.x);
        n0.y = fmaf(c, a.y, -s * b.y);
        n1.x = fmaf(s, a.x,  c * b.x);
        n1.y = fmaf(s, a.y,  c * b.y);
        v[j0] = n0; v[j1] = n1;
    }
}

__global__ void __launch_bounds__(TPB, 4)
quantum_kernel(const float* __restrict__ x,
               const float* __restrict__ weights,
               const float* __restrict__ Wlin,
               const float* __restrict__ bias_p,
               float* __restrict__ out)
{
    __shared__ float2 psi[DIM + (DIM >> 4)];                 // ~34 KB padded state
    __shared__ float  ryc[NL][NQ], rys[NL][NQ];              // Ry cos/sin
    __shared__ float  phi05[NL][NQ], om05[NL][NQ];           // half-angles for diagonals
    __shared__ float2 DphiHi[NL][64], DphiLo[NL][64];        // Pi Rz(phi) split tables
    __shared__ float2 DomHi[NL][64],  DomLo[NL][64];         // Pi Rz(omega) split tables
    __shared__ unsigned short srcHi[NL][64], srcLo[NL][64];  // CNOT-layer perm (GF2 split)
    __shared__ float2 PhiC[64], PloC[64];                    // complex init tables (embed * Dphi[0])
    __shared__ float  Thi[64], Tlo[64];                      // signed-weight readout tables
    __shared__ float  cw[NQ], sw[NQ], Wv[NQ];
    __shared__ float  red[TPB / 32];

    const int tid = threadIdx.x;
    const int bidx = blockIdx.x;

    // ---------- Phase 1: embedding trig, Ry constants, diag half-angles, CNOT tables ----------
    if (tid < NQ) {
        float h = 0.5f * x[bidx * NQ + tid];
        sincosf(h, &sw[tid], &cw[tid]);
        Wv[tid] = Wlin[tid];
    }
    for (int idx = tid; idx < NL * NQ; idx += TPB) {
        const int l = idx / NQ, w = idx % NQ;
        const float* wp = weights + (l * NQ + w) * 3;
        float st, ct; sincosf(0.5f * wp[1], &st, &ct);
        ryc[l][w] = ct; rys[l][w] = st;
        phi05[l][w] = 0.5f * wp[0];
        om05[l][w]  = 0.5f * wp[2];
    }
    for (int idx = tid; idx < NL * 128; idx += TPB) {
        const int l = idx >> 7, k = idx & 127;
        const int r = l % (NQ - 1) + 1;
        unsigned v = (k < 64) ? (unsigned)k : ((unsigned)(k - 64) << 6);
        for (int w = NQ - 1; w >= 0; --w) {
            const int t = (w + r) % NQ;
            v ^= ((v >> (NQ - 1 - w)) & 1u) << (NQ - 1 - t);
        }
        if (k < 64) srcLo[l][k] = (unsigned short)v;
        else        srcHi[l][k - 64] = (unsigned short)v;
    }
    __syncthreads();

    // ---------- Phase 2: diagonal phase tables. Rz(a) = diag(e^{-ia/2}, e^{+ia/2}) ----------
    for (int idx = tid; idx < NL * 4 * 64; idx += TPB) {
        const int l = idx >> 8;
        const int which = (idx >> 6) & 3;       // 0 phiHi, 1 phiLo, 2 omHi, 3 omLo
        const int e = idx & 63;
        const float* ang = (which < 2) ? &phi05[l][0] : &om05[l][0];
        const int base = (which & 1) ? 6 : 0;   // lo half covers wires 6..11
        float a = 0.f;
#pragma unroll
        for (int w = 0; w < 6; ++w) {
            const float aw = ang[base + w];
            a += ((e >> (5 - w)) & 1) ? aw : -aw;
        }
        float sn, cs; sincosf(a, &sn, &cs);
        const float2 ph = make_float2(cs, sn);
        if      (which == 0) DphiHi[l][e] = ph;
        else if (which == 1) DphiLo[l][e] = ph;
        else if (which == 2) DomHi[l][e]  = ph;
        else                 DomLo[l][e]  = ph;
    }
    __syncthreads();

    // ---------- Phase 3: complex init tables (embedding * layer-0 phi diag), readout tables ----------
    if (tid < 64) {
        const int j = tid;
        float ph = 1.f, pl = 1.f, th = 0.f, tl = 0.f;
#pragma unroll
        for (int w = 0; w < 6; ++w) {
            const int b = (j >> (5 - w)) & 1;
            ph *= b ? sw[w] : cw[w];
            th += b ? -Wv[w] : Wv[w];
            pl *= b ? sw[6 + w] : cw[6 + w];
            tl += b ? -Wv[6 + w] : Wv[6 + w];
        }
        PhiC[j] = make_float2(ph * DphiHi[0][j].x, ph * DphiHi[0][j].y);
        PloC[j] = make_float2(pl * DphiLo[0][j].x, pl * DphiLo[0][j].y);
        Thi[j] = th; Tlo[j] = tl;
    }
    __syncthreads();

    // ---------- Circuit: per layer: gather(C_{l-1} + Dphi_l) -> 12 Ry in 3 passes -> scatter(Dom_l) ----------
    float2 v[16];
#pragma unroll 1
    for (int l = 0; l < NL; ++l) {
        // ---- Pass A gather: wires 8..11 (low 4 index bits)
        if (l == 0) {
#pragma unroll
            for (int j = 0; j < 16; ++j) {
                const int i = (tid << 4) | j;
                v[j] = cmul(PhiC[i >> 6], PloC[i & 63]);
            }
        } else {
#pragma unroll
            for (int j = 0; j < 16; ++j) {
                const int i = (tid << 4) | j;
                const int s = srcHi[l - 1][i >> 6] ^ srcLo[l - 1][i & 63];
                const float2 d = cmul(DphiHi[l][i >> 6], DphiLo[l][i & 63]);
                v[j] = cmul(d, psi[SLOT(s)]);
            }
            __syncthreads();   // scattered reads must complete before overwriting
        }
        apply_ry<3>(v, ryc[l][8],  rys[l][8]);
        apply_ry<2>(v, ryc[l][9],  rys[l][9]);
        apply_ry<1>(v, ryc[l][10], rys[l][10]);
        apply_ry<0>(v, ryc[l][11], rys[l][11]);
#pragma unroll
        for (int j = 0; j < 16; ++j) psi[SLOT((tid << 4) | j)] = v[j];
        __syncthreads();

        // ---- Pass B: wires 4..7 (index bits 7..4)
#pragma unroll
        for (int j = 0; j < 16; ++j) {
            const int i = ((tid & 0xF0) << 4) | (j << 4) | (tid & 15);
            v[j] = psi[SLOT(i)];
        }
        apply_ry<3>(v, ryc[l][4], rys[l][4]);
        apply_ry<2>(v, ryc[l][5], rys[l][5]);
        apply_ry<1>(v, ryc[l][6], rys[l][6]);
        apply_ry<0>(v, ryc[l][7], rys[l][7]);
#pragma unroll
        for (int j = 0; j < 16; ++j) {
            const int i = ((tid & 0xF0) << 4) | (j << 4) | (tid & 15);
            psi[SLOT(i)] = v[j];
        }
        __syncthreads();

        // ---- Pass C: wires 0..3 (index bits 11..8); scatter applies omega diagonal
#pragma unroll
        for (int j = 0; j < 16; ++j) {
            const int i = (j << 8) | tid;
            v[j] = psi[SLOT(i)];
        }
        apply_ry<3>(v, ryc[l][0], rys[l][0]);
        apply_ry<2>(v, ryc[l][1], rys[l][1]);
        apply_ry<1>(v, ryc[l][2], rys[l][2]);
        apply_ry<0>(v, ryc[l][3], rys[l][3]);
        if (l < NL - 1) {
            // apply Dom_l at scatter; final layer's omega diagonal is a pure phase -> dropped
#pragma unroll
            for (int j = 0; j < 16; ++j) {
                const int i = (j << 8) | tid;
                const float2 d = cmul(DomHi[l][i >> 6], DomLo[l][i & 63]);
                psi[SLOT(i)] = cmul(d, v[j]);
            }
        } else {
#pragma unroll
            for (int j = 0; j < 16; ++j) {
                const int i = (j << 8) | tid;
                psi[SLOT(i)] = v[j];
            }
        }
        __syncthreads();
    }

    // ---------- Readout: final CNOT perm fused into gather; probs * signed-weight table ----------
    float acc = 0.f;
#pragma unroll
    for (int j = 0; j < 16; ++j) {
        const int i = (tid << 4) | j;
        const int s = srcHi[NL - 1][i >> 6] ^ srcLo[NL - 1][i & 63];
        const float2 a = psi[SLOT(s)];
        acc = fmaf(fmaf(a.x, a.x, a.y * a.y), Thi[i >> 6] + Tlo[i & 63], acc);
    }
#pragma unroll
    for (int o = 16; o; o >>= 1) acc += __shfl_xor_sync(0xFFFFFFFFu, acc, o);
    if ((tid & 31) == 0) red[tid >> 5] = acc;
    __syncthreads();
    if (tid == 0) {
        float s = 0.f;
#pragma unroll
        for (int k = 0; k < TPB / 32; ++k) s += red[k];
        out[bidx] = s + bias_p[0];
    }
}

extern "C" void kernel_launch(void* const* d_in, const int* in_sizes, int n_in,
                              void* d_out, int out_size)
{
    const float* x       = (const float*)d_in[0];
    const float* weights = (const float*)d_in[1];
    const float* W       = (const float*)d_in[2];
    const float* b       = (const float*)d_in[3];
    float* out = (float*)d_out;
    quantum_kernel<<<512, TPB>>>(x, weights, W, b, out);
}

// round 10
// speedup vs baseline: 1.0687x; 1.0687x over previous
#include <cuda_runtime.h>

#define NQ   12
#define DIM  4096
#define NL   6
#define TPB  256

// padded smem slot to avoid bank conflicts in the stride-16 pass
#define SLOT(i) ((i) + ((i) >> 4))

struct Smem {
    float2 psi[2][DIM + (DIM >> 4)];                  // two padded states, ~66.5 KB
    float2 DphiHi[NL][64], DphiLo[NL][64];            // Pi Rz(phi) split tables
    float2 DomHi[NL][64],  DomLo[NL][64];             // Pi Rz(omega) split tables
    float2 PhiC[2][64], PloC[2][64];                  // per-state complex init tables
    unsigned short srcHi[NL][64], srcLo[NL][64];      // CNOT-layer perm (GF2 split)
    float  ryc[NL][NQ], rys[NL][NQ];                  // Ry cos/sin
    float  phi05[NL][NQ], om05[NL][NQ];               // half-angles for diagonals
    float  Thi[64], Tlo[64];                          // signed-weight readout tables
    float  cw[2][NQ], sw[2][NQ], Wv[NQ];
    float  red[2][TPB / 32];
};

__device__ __forceinline__ float2 cmul(const float2 a, const float2 b) {
    float2 r;
    r.x = fmaf(a.x, b.x, -a.y * b.y);
    r.y = fmaf(a.x, b.y,  a.y * b.x);
    return r;
}

// Real Ry butterfly on pairing bit P: [c -s; s c] applied to (re,im) independently.
template <int P>
__device__ __forceinline__ void apply_ry(float2 v[16], const float c, const float s) {
#pragma unroll
    for (int j0 = 0; j0 < 16; ++j0) {
        if (j0 & (1 << P)) continue;
        const int j1 = j0 | (1 << P);
        const float2 a = v[j0], b = v[j1];
        float2 n0, n1;
        n0.x = fmaf(c, a.x, -s * b.x);
        n0.y = fmaf(c, a.y, -s * b.y);
        n1.x = fmaf(s, a.x,  c * b.x);
        n1.y = fmaf(s, a.y,  c * b.y);
        v[j0] = n0; v[j1] = n1;
    }
}

__global__ void __launch_bounds__(TPB, 2)
quantum_kernel(const float* __restrict__ x,
               const float* __restrict__ weights,
               const float* __restrict__ Wlin,
               const float* __restrict__ bias_p,
               float* __restrict__ out)
{
    extern __shared__ unsigned char smem_raw[];
    Smem* sm = reinterpret_cast<Smem*>(smem_raw);

    const int tid = threadIdx.x;
    const int bidx = blockIdx.x;          // this CTA handles batches 2*bidx and 2*bidx+1

    // ---------- Phase 1: embedding trig (both states), Ry constants, half-angles, CNOT tables ----------
    if (tid < 2 * NQ) {
        const int s = tid / NQ, w = tid % NQ;
        float h = 0.5f * x[(2 * bidx + s) * NQ + w];
        sincosf(h, &sm->sw[s][w], &sm->cw[s][w]);
        if (s == 0) sm->Wv[w] = Wlin[w];
    }
    for (int idx = tid; idx < NL * NQ; idx += TPB) {
        const int l = idx / NQ, w = idx % NQ;
        const float* wp = weights + (l * NQ + w) * 3;
        float st, ct; sincosf(0.5f * wp[1], &st, &ct);
        sm->ryc[l][w] = ct; sm->rys[l][w] = st;
        sm->phi05[l][w] = 0.5f * wp[0];
        sm->om05[l][w]  = 0.5f * wp[2];
    }
    for (int idx = tid; idx < NL * 128; idx += TPB) {
        const int l = idx >> 7, k = idx & 127;
        const int r = l % (NQ - 1) + 1;
        unsigned v = (k < 64) ? (unsigned)k : ((unsigned)(k - 64) << 6);
        for (int w = NQ - 1; w >= 0; --w) {
            const int t = (w + r) % NQ;
            v ^= ((v >> (NQ - 1 - w)) & 1u) << (NQ - 1 - t);
        }
        if (k < 64) sm->srcLo[l][k] = (unsigned short)v;
        else        sm->srcHi[l][k - 64] = (unsigned short)v;
    }
    __syncthreads();

    // ---------- Phase 2: diagonal phase tables. Rz(a) = diag(e^{-ia/2}, e^{+ia/2}) ----------
    for (int idx = tid; idx < NL * 4 * 64; idx += TPB) {
        const int l = idx >> 8;
        const int which = (idx >> 6) & 3;       // 0 phiHi, 1 phiLo, 2 omHi, 3 omLo
        const int e = idx & 63;
        const float* ang = (which < 2) ? &sm->phi05[l][0] : &sm->om05[l][0];
        const int base = (which & 1) ? 6 : 0;   // lo half covers wires 6..11
        float a = 0.f;
#pragma unroll
        for (int w = 0; w < 6; ++w) {
            const float aw = ang[base + w];
            a += ((e >> (5 - w)) & 1) ? aw : -aw;
        }
        float sn, cs; sincosf(a, &sn, &cs);
        const float2 ph = make_float2(cs, sn);
        if      (which == 0) sm->DphiHi[l][e] = ph;
        else if (which == 1) sm->DphiLo[l][e] = ph;
        else if (which == 2) sm->DomHi[l][e]  = ph;
        else                 sm->DomLo[l][e]  = ph;
    }
    __syncthreads();

    // ---------- Phase 3: per-state init tables (embedding * layer-0 phi diag), readout tables ----------
    if (tid < 128) {
        const int s = tid >> 6, j = tid & 63;
        float ph = 1.f, pl = 1.f, th = 0.f, tl = 0.f;
#pragma unroll
        for (int w = 0; w < 6; ++w) {
            const int b = (j >> (5 - w)) & 1;
            ph *= b ? sm->sw[s][w] : sm->cw[s][w];
            pl *= b ? sm->sw[s][6 + w] : sm->cw[s][6 + w];
            th += b ? -sm->Wv[w] : sm->Wv[w];
            tl += b ? -sm->Wv[6 + w] : sm->Wv[6 + w];
        }
        sm->PhiC[s][j] = make_float2(ph * sm->DphiHi[0][j].x, ph * sm->DphiHi[0][j].y);
        sm->PloC[s][j] = make_float2(pl * sm->DphiLo[0][j].x, pl * sm->DphiLo[0][j].y);
        if (s == 0) { sm->Thi[j] = th; sm->Tlo[j] = tl; }
    }
    __syncthreads();

    // ---------- Circuit: per layer: gather(perm + Dphi_l) -> 12 Ry in 3 passes -> scatter(Dom_l) ----------
    float2 v[16];
#pragma unroll 1
    for (int l = 0; l < NL; ++l) {
        // ---- Pass A: wires 8..11 (low 4 index bits); gather applies previous layer's CNOT perm
#pragma unroll 1
        for (int s = 0; s < 2; ++s) {
            if (l == 0) {
#pragma unroll
                for (int j = 0; j < 16; ++j) {
                    const int i = (tid << 4) | j;
                    v[j] = cmul(sm->PhiC[s][i >> 6], sm->PloC[s][i & 63]);
                }
            } else {
#pragma unroll
                for (int j = 0; j < 16; ++j) {
                    const int i = (tid << 4) | j;
                    const int sc = sm->srcHi[l - 1][i >> 6] ^ sm->srcLo[l - 1][i & 63];
                    const float2 d = cmul(sm->DphiHi[l][i >> 6], sm->DphiLo[l][i & 63]);
                    v[j] = cmul(d, sm->psi[s][SLOT(sc)]);
                }
                __syncthreads();   // all scattered reads of psi[s] done before overwrite
            }
            apply_ry<3>(v, sm->ryc[l][8],  sm->rys[l][8]);
            apply_ry<2>(v, sm->ryc[l][9],  sm->rys[l][9]);
            apply_ry<1>(v, sm->ryc[l][10], sm->rys[l][10]);
            apply_ry<0>(v, sm->ryc[l][11], sm->rys[l][11]);
#pragma unroll
            for (int j = 0; j < 16; ++j) sm->psi[s][SLOT((tid << 4) | j)] = v[j];
        }
        __syncthreads();

        // ---- Pass B: wires 4..7 (index bits 7..4); thread-private slot sets, no intra sync
#pragma unroll 1
        for (int s = 0; s < 2; ++s) {
#pragma unroll
            for (int j = 0; j < 16; ++j) {
                const int i = ((tid & 0xF0) << 4) | (j << 4) | (tid & 15);
                v[j] = sm->psi[s][SLOT(i)];
            }
            apply_ry<3>(v, sm->ryc[l][4], sm->rys[l][4]);
            apply_ry<2>(v, sm->ryc[l][5], sm->rys[l][5]);
            apply_ry<1>(v, sm->ryc[l][6], sm->rys[l][6]);
            apply_ry<0>(v, sm->ryc[l][7], sm->rys[l][7]);
#pragma unroll
            for (int j = 0; j < 16; ++j) {
                const int i = ((tid & 0xF0) << 4) | (j << 4) | (tid & 15);
                sm->psi[s][SLOT(i)] = v[j];
            }
        }
        __syncthreads();

        // ---- Pass C: wires 0..3 (index bits 11..8); scatter applies omega diagonal
#pragma unroll 1
        for (int s = 0; s < 2; ++s) {
#pragma unroll
            for (int j = 0; j < 16; ++j) {
                const int i = (j << 8) | tid;
                v[j] = sm->psi[s][SLOT(i)];
            }
            apply_ry<3>(v, sm->ryc[l][0], sm->rys[l][0]);
            apply_ry<2>(v, sm->ryc[l][1], sm->rys[l][1]);
            apply_ry<1>(v, sm->ryc[l][2], sm->rys[l][2]);
            apply_ry<0>(v, sm->ryc[l][3], sm->rys[l][3]);
            if (l < NL - 1) {
                // apply Dom_l at scatter; final layer's omega diagonal is a pure phase -> dropped
#pragma unroll
                for (int j = 0; j < 16; ++j) {
                    const int i = (j << 8) | tid;
                    const float2 d = cmul(sm->DomHi[l][i >> 6], sm->DomLo[l][i & 63]);
                    sm->psi[s][SLOT(i)] = cmul(d, v[j]);
                }
            } else {
#pragma unroll
                for (int j = 0; j < 16; ++j) {
                    const int i = (j << 8) | tid;
                    sm->psi[s][SLOT(i)] = v[j];
                }
            }
        }
        __syncthreads();
    }

    // ---------- Readout: final CNOT perm fused into gather; probs * signed-weight table ----------
#pragma unroll 1
    for (int s = 0; s < 2; ++s) {
        float acc = 0.f;
#pragma unroll
        for (int j = 0; j < 16; ++j) {
            const int i = (tid << 4) | j;
            const int sc = sm->srcHi[NL - 1][i >> 6] ^ sm->srcLo[NL - 1][i & 63];
            const float2 a = sm->psi[s][SLOT(sc)];
            acc = fmaf(fmaf(a.x, a.x, a.y * a.y), sm->Thi[i >> 6] + sm->Tlo[i & 63], acc);
        }
#pragma unroll
        for (int o = 16; o; o >>= 1) acc += __shfl_xor_sync(0xFFFFFFFFu, acc, o);
        if ((tid & 31) == 0) sm->red[s][tid >> 5] = acc;
    }
    __syncthreads();
    if (tid < 2) {
        float ssum = 0.f;
#pragma unroll
        for (int k = 0; k < TPB / 32; ++k) ssum += sm->red[tid][k];
        out[2 * bidx + tid] = ssum + bias_p[0];
    }
}

extern "C" void kernel_launch(void* const* d_in, const int* in_sizes, int n_in,
                              void* d_out, int out_size)
{
    const float* x       = (const float*)d_in[0];
    const float* weights = (const float*)d_in[1];
    const float* W       = (const float*)d_in[2];
    const float* b       = (const float*)d_in[3];
    float* out = (float*)d_out;

    cudaFuncSetAttribute(quantum_kernel,
                         cudaFuncAttributeMaxDynamicSharedMemorySize,
                         (int)sizeof(Smem));
    quantum_kernel<<<256, TPB, sizeof(Smem)>>>(x, weights, W, b, out);
}

// round 13
// speedup vs baseline: 1.1499x; 1.0760x over previous
#include <cuda_runtime.h>

#define NQ   12
#define DIM  4096
#define NL   6
#define TPB  256

// padded smem slot to avoid bank conflicts in strided passes
#define SLOT(i) ((i) + ((i) >> 4))

struct Smem {
    float2 psi[2][DIM + (DIM >> 4)];                  // two padded states, ~66.5 KB
    float2 DphiHi[NL][64], DphiLo[NL][64];            // Pi Rz(phi) split tables
    float2 DomHi[NL][64],  DomLo[NL][64];             // Pi Rz(omega) split tables
    float2 PhiC[2][64], PloC[2][64];                  // per-state complex init tables
    unsigned short fwdHi[NL][64], fwdLo[NL][64];      // FORWARD CNOT-layer perm (GF2 split)
    float  ryc[NL][NQ], rys[NL][NQ];                  // Ry cos/sin
    float  phi05[NL][NQ], om05[NL][NQ];               // half-angles for diagonals
    float  Thi[64], Tlo[64];                          // signed-weight readout tables
    float  cw[2][NQ], sw[2][NQ], Wv[NQ];
    float  red[2][TPB / 32];
};

__device__ __forceinline__ float2 cmul(const float2 a, const float2 b) {
    float2 r;
    r.x = fmaf(a.x, b.x, -a.y * b.y);
    r.y = fmaf(a.x, b.y,  a.y * b.x);
    return r;
}

// Real Ry butterfly on register-pairing bit P.
template <int P>
__device__ __forceinline__ void apply_ry(float2 v[16], const float c, const float s) {
#pragma unroll
    for (int j0 = 0; j0 < 16; ++j0) {
        if (j0 & (1 << P)) continue;
        const int j1 = j0 | (1 << P);
        const float2 a = v[j0], b = v[j1];
        float2 n0, n1;
        n0.x = fmaf(c, a.x, -s * b.x);
        n0.y = fmaf(c, a.y, -s * b.y);
        n1.x = fmaf(s, a.x,  c * b.x);
        n1.y = fmaf(s, a.y,  c * b.y);
        v[j0] = n0; v[j1] = n1;
    }
}

// Real Ry butterfly across lanes: pairing on thread bit TB (within warp, no smem/sync).
// side0: n = c*a - s*b ; side1: n = s*a + c*b  ->  n = c*own + ks*other, ks = bit? +s : -s
template <int TB>
__device__ __forceinline__ void apply_ry_shfl(float2 v[16], const float c, const float s,
                                              const int tid) {
    const float ks = ((tid >> TB) & 1) ? s : -s;
#pragma unroll
    for (int j = 0; j < 16; ++j) {
        const float ox = __shfl_xor_sync(0xFFFFFFFFu, v[j].x, 1 << TB);
        const float oy = __shfl_xor_sync(0xFFFFFFFFu, v[j].y, 1 << TB);
        v[j].x = fmaf(ks, ox, c * v[j].x);
        v[j].y = fmaf(ks, oy, c * v[j].y);
    }
}

__global__ void __launch_bounds__(TPB, 2)
quantum_kernel(const float* __restrict__ x,
               const float* __restrict__ weights,
               const float* __restrict__ Wlin,
               const float* __restrict__ bias_p,
               float* __restrict__ out)
{
    extern __shared__ unsigned char smem_raw[];
    Smem* sm = reinterpret_cast<Smem*>(smem_raw);

    const int tid = threadIdx.x;
    const int bidx = blockIdx.x;          // this CTA handles batches 2*bidx and 2*bidx+1

    // ---------- Phase 1: embedding trig (both states), Ry constants, half-angles, FWD CNOT tables ----------
    if (tid < 2 * NQ) {
        const int s = tid / NQ, w = tid % NQ;
        float h = 0.5f * x[(2 * bidx + s) * NQ + w];
        sincosf(h, &sm->sw[s][w], &sm->cw[s][w]);
        if (s == 0) sm->Wv[w] = Wlin[w];
    }
    for (int idx = tid; idx < NL * NQ; idx += TPB) {
        const int l = idx / NQ, w = idx % NQ;
        const float* wp = weights + (l * NQ + w) * 3;
        float st, ct; sincosf(0.5f * wp[1], &st, &ct);
        sm->ryc[l][w] = ct; sm->rys[l][w] = st;
        sm->phi05[l][w] = 0.5f * wp[0];
        sm->om05[l][w]  = 0.5f * wp[2];
    }
    // FORWARD permutation (scatter direction): dst(i) = f_11(...f_1(f_0(i))),
    // i.e. apply CNOT(w, (w+r)%NQ) for w = 0..11 ascending, tracking the live index.
    for (int idx = tid; idx < NL * 128; idx += TPB) {
        const int l = idx >> 7, k = idx & 127;
        const int r = l % (NQ - 1) + 1;
        unsigned v = (k < 64) ? (unsigned)k : ((unsigned)(k - 64) << 6);
        for (int w = 0; w < NQ; ++w) {
            const int t = (w + r) % NQ;
            v ^= ((v >> (NQ - 1 - w)) & 1u) << (NQ - 1 - t);
        }
        if (k < 64) sm->fwdLo[l][k] = (unsigned short)v;
        else        sm->fwdHi[l][k - 64] = (unsigned short)v;
    }
    __syncthreads();

    // ---------- Phase 2: diagonal phase tables. Rz(a) = diag(e^{-ia/2}, e^{+ia/2}) ----------
    for (int idx = tid; idx < NL * 4 * 64; idx += TPB) {
        const int l = idx >> 8;
        const int which = (idx >> 6) & 3;       // 0 phiHi, 1 phiLo, 2 omHi, 3 omLo
        const int e = idx & 63;
        const float* ang = (which < 2) ? &sm->phi05[l][0] : &sm->om05[l][0];
        const int base = (which & 1) ? 6 : 0;   // lo half covers wires 6..11
        float a = 0.f;
#pragma unroll
        for (int w = 0; w < 6; ++w) {
            const float aw = ang[base + w];
            a += ((e >> (5 - w)) & 1) ? aw : -aw;
        }
        float sn, cs; sincosf(a, &sn, &cs);
        const float2 ph = make_float2(cs, sn);
        if      (which == 0) sm->DphiHi[l][e] = ph;
        else if (which == 1) sm->DphiLo[l][e] = ph;
        else if (which == 2) sm->DomHi[l][e]  = ph;
        else                 sm->DomLo[l][e]  = ph;
    }
    __syncthreads();

    // ---------- Phase 3: per-state init tables (embedding * layer-0 phi diag), readout tables ----------
    if (tid < 128) {
        const int s = tid >> 6, j = tid & 63;
        float ph = 1.f, pl = 1.f, th = 0.f, tl = 0.f;
#pragma unroll
        for (int w = 0; w < 6; ++w) {
            const int b = (j >> (5 - w)) & 1;
            ph *= b ? sm->sw[s][w] : sm->cw[s][w];
            pl *= b ? sm->sw[s][6 + w] : sm->cw[s][6 + w];
            th += b ? -sm->Wv[w] : sm->Wv[w];
            tl += b ? -sm->Wv[6 + w] : sm->Wv[6 + w];
        }
        sm->PhiC[s][j] = make_float2(ph * sm->DphiHi[0][j].x, ph * sm->DphiHi[0][j].y);
        sm->PloC[s][j] = make_float2(pl * sm->DphiLo[0][j].x, pl * sm->DphiLo[0][j].y);
        if (s == 0) { sm->Thi[j] = th; sm->Tlo[j] = tl; }
    }
    __syncthreads();

    // ---------- Circuit ----------
    // Per layer: [linear load + Dphi, gates w8..11 (regs), gates w4..7 (shfl), linear store]
    //            sync
    //            [transposed load, gates w0..3 (regs), SYNC, Dom + SCATTER through fwd perm]
    //            sync
    float2 v[16];
#pragma unroll 1
    for (int l = 0; l < NL; ++l) {
        // ---- Pass A: amp bits 0-3 in regs (wires 8-11), tid bits 0-3 = amp bits 4-7 (wires 4-7)
        //      thread-private slot set: no intra-pass hazard
#pragma unroll 1
        for (int s = 0; s < 2; ++s) {
            if (l == 0) {
                const float2 ph = sm->PhiC[s][tid >> 2];
#pragma unroll
                for (int j = 0; j < 16; ++j)
                    v[j] = cmul(ph, sm->PloC[s][((tid & 3) << 4) | j]);
            } else {
                const float2 dh = sm->DphiHi[l][tid >> 2];
#pragma unroll
                for (int j = 0; j < 16; ++j) {
                    const float2 d = cmul(dh, sm->DphiLo[l][((tid & 3) << 4) | j]);
                    v[j] = cmul(d, sm->psi[s][SLOT((tid << 4) | j)]);
                }
            }
            apply_ry<3>(v, sm->ryc[l][8],  sm->rys[l][8]);    // wire 8  -> amp bit 3
            apply_ry<2>(v, sm->ryc[l][9],  sm->rys[l][9]);    // wire 9  -> amp bit 2
            apply_ry<1>(v, sm->ryc[l][10], sm->rys[l][10]);   // wire 10 -> amp bit 1
            apply_ry<0>(v, sm->ryc[l][11], sm->rys[l][11]);   // wire 11 -> amp bit 0
            apply_ry_shfl<3>(v, sm->ryc[l][4], sm->rys[l][4], tid);  // wire 4 -> amp bit 7 -> tid bit 3
            apply_ry_shfl<2>(v, sm->ryc[l][5], sm->rys[l][5], tid);  // wire 5 -> tid bit 2
            apply_ry_shfl<1>(v, sm->ryc[l][6], sm->rys[l][6], tid);  // wire 6 -> tid bit 1
            apply_ry_shfl<0>(v, sm->ryc[l][7], sm->rys[l][7], tid);  // wire 7 -> tid bit 0
#pragma unroll
            for (int j = 0; j < 16; ++j) sm->psi[s][SLOT((tid << 4) | j)] = v[j];
        }
        __syncthreads();

        // ---- Pass C: amp bits 8-11 in regs (wires 0-3); scatter applies Dom + forward CNOT perm.
        //      Scatter destinations overlap other threads' load slots -> barrier between
        //      the block-wide loads and any scatter store (this was the R12 race).
#pragma unroll 1
        for (int s = 0; s < 2; ++s) {
#pragma unroll
            for (int j = 0; j < 16; ++j)
                v[j] = sm->psi[s][SLOT((j << 8) | tid)];
            apply_ry<3>(v, sm->ryc[l][0], sm->rys[l][0]);     // wire 0 -> amp bit 11 -> j bit 3
            apply_ry<2>(v, sm->ryc[l][1], sm->rys[l][1]);
            apply_ry<1>(v, sm->ryc[l][2], sm->rys[l][2]);
            apply_ry<0>(v, sm->ryc[l][3], sm->rys[l][3]);
            __syncthreads();   // all loads of psi[s] complete before any scatter into psi[s]
            const int lo6 = tid & 63;
            const unsigned short fl = sm->fwdLo[l][lo6];
            if (l < NL - 1) {
                const float2 dlo = sm->DomLo[l][lo6];
#pragma unroll
                for (int j = 0; j < 16; ++j) {
                    const int hi6 = (j << 2) | (tid >> 6);
                    const int dst = sm->fwdHi[l][hi6] ^ fl;
                    const float2 d = cmul(sm->DomHi[l][hi6], dlo);
                    sm->psi[s][SLOT(dst)] = cmul(d, v[j]);
                }
            } else {
                // final layer: omega diagonal is a pure phase before |psi|^2 -> dropped
#pragma unroll
                for (int j = 0; j < 16; ++j) {
                    const int dst = sm->fwdHi[l][(j << 2) | (tid >> 6)] ^ fl;
                    sm->psi[s][SLOT(dst)] = v[j];
                }
            }
        }
        __syncthreads();
    }

    // ---------- Readout: state already in final order; probs * signed-weight table ----------
#pragma unroll 1
    for (int s = 0; s < 2; ++s) {
        const float th = sm->Thi[tid >> 2];
        float acc = 0.f;
#pragma unroll
        for (int j = 0; j < 16; ++j) {
            const float2 a = sm->psi[s][SLOT((tid << 4) | j)];
            acc = fmaf(fmaf(a.x, a.x, a.y * a.y),
                       th + sm->Tlo[((tid & 3) << 4) | j], acc);
        }
#pragma unroll
        for (int o = 16; o; o >>= 1) acc += __shfl_xor_sync(0xFFFFFFFFu, acc, o);
        if ((tid & 31) == 0) sm->red[s][tid >> 5] = acc;
    }
    __syncthreads();
    if (tid < 2) {
        float ssum = 0.f;
#pragma unroll
        for (int k = 0; k < TPB / 32; ++k) ssum += sm->red[tid][k];
        out[2 * bidx + tid] = ssum + bias_p[0];
    }
}

extern "C" void kernel_launch(void* const* d_in, const int* in_sizes, int n_in,
                              void* d_out, int out_size)
{
    const float* x       = (const float*)d_in[0];
    const float* weights = (const float*)d_in[1];
    const float* W       = (const float*)d_in[2];
    const float* b       = (const float*)d_in[3];
    float* out = (float*)d_out;

    cudaFuncSetAttribute(quantum_kernel,
                         cudaFuncAttributeMaxDynamicSharedMemorySize,
                         (int)sizeof(Smem));
    quantum_kernel<<<256, TPB, sizeof(Smem)>>>(x, weights, W, b, out);
}